// round 15
// baseline (speedup 1.0000x reference)
#include <cuda_runtime.h>
#include <math.h>

// Shapes
// x:  [32, 112, 112, 128] fp32  -> B=32, HW=12544, C=128
// w1: [128, 2048], b1: [2048], w2: [2048, 128], b2: [128]
#define B      32
#define HW     12544
#define C      128
#define R      2048
#define NSPLIT 98
#define NTOTAL (B * NSPLIT)                  // 3136 splits
#define F4_PER_B  (HW * C / 4)               // 401408 float4 per batch
#define F4_PER_BLK (128 * C / 4)             // 4096 float4 per split
#define RBLKS  (R / 128)                     // 16 excite blocks per batch

// Scratch (device globals: allocation-free)
__device__ __align__(16) float g_partial[NTOTAL * C];   // 1.6 MB pool partials
__device__ __align__(16) float g_gp[B * RBLKS * C];     // gate partials, 256 KB

// ---------------------------------------------------------------------------
// Kernel 1: partial pooling sums.  grid (NSPLIT, B), 256 threads.
// Body identical to the proven R5 kernel; adds only the PDL trigger after
// the final store so the excite kernel may launch early.
// ---------------------------------------------------------------------------
__global__ __launch_bounds__(256, 8)
void se_pool_kernel(const float* __restrict__ x) {
    const int b = blockIdx.y;
    const int split = blockIdx.x;
    const float4* __restrict__ xb =
        reinterpret_cast<const float4*>(x) + (size_t)b * F4_PER_B + (size_t)split * F4_PER_BLK;
    const int t = threadIdx.x;

    float4 acc = make_float4(0.f, 0.f, 0.f, 0.f);
#pragma unroll
    for (int i = 0; i < 16; i++) {           // 16 * 256 = 4096 float4
        float4 v = xb[t + i * 256];
        acc.x += v.x; acc.y += v.y; acc.z += v.z; acc.w += v.w;
    }

    __shared__ float4 sh[256];
    sh[t] = acc;
    __syncthreads();

    if (t < 32) {
        float4 s = sh[t];
#pragma unroll
        for (int j = 1; j < 8; j++) {
            float4 v = sh[t + j * 32];
            s.x += v.x; s.y += v.y; s.z += v.z; s.w += v.w;
        }
        reinterpret_cast<float4*>(g_partial)[(size_t)(b * NSPLIT + split) * 32 + t] = s;
    }
    __syncthreads();                         // all block writes precede triggers
    cudaTriggerProgrammaticLaunchCompletion();
}

// ---------------------------------------------------------------------------
// Kernel 2: fused excite.  grid (RBLKS=16, B), 128 threads.  PDL dependent:
// waits on pool completion at entry, triggers for scale after its store.
// ---------------------------------------------------------------------------
__global__ __launch_bounds__(128, 8)
void se_excite_kernel(const float* __restrict__ w1, const float* __restrict__ b1,
                      const float* __restrict__ w2) {
    cudaGridDependencySynchronize();         // pool's g_partial now visible

    const int b = blockIdx.y;
    const int rblk = blockIdx.x;
    const int t = threadIdx.x;

    __shared__ float s[C];
    __shared__ float h[128];

    // a) reduce this batch's pool partials (50 KB, L2-hit) -> mean
    {
        const float* p = g_partial + (size_t)b * NSPLIT * C + t;
        float acc = 0.f;
#pragma unroll 14
        for (int k = 0; k < NSPLIT; k++) acc += p[(size_t)k * C];
        s[t] = acc * (1.0f / (float)HW);
    }
    __syncthreads();

    // b) GEMM1 + tanh-approx GELU: one r per thread (coalesced w1 columns)
    {
        const int r = rblk * 128 + t;
        float acc = b1[r];
#pragma unroll 16
        for (int c = 0; c < C; c++) acc += s[c] * w1[(size_t)c * R + r];
        float u = acc;
        float inner = 0.7978845608028654f * (u + 0.044715f * u * u * u);
        h[t] = 0.5f * u * (1.0f + tanhf(inner));
    }
    __syncthreads();

    // c) GEMM2 partial for this r-chunk (one c per thread, coalesced w2 rows)
    {
        const float* w2s = w2 + (size_t)(rblk * 128) * C + t;
        float acc = 0.f;
#pragma unroll 16
        for (int rr = 0; rr < 128; rr++) acc += h[rr] * w2s[(size_t)rr * C];
        g_gp[((size_t)b * RBLKS + rblk) * C + t] = acc;
    }
    __syncthreads();
    cudaTriggerProgrammaticLaunchCompletion();
}

// ---------------------------------------------------------------------------
// Kernel 3: scale with fused gate finalize.  grid (NTOTAL), 256 threads.
// PDL dependent: parks in griddepsync while excite finishes, then runs the
// proven R5 body (reversed traversal, __ldcs/__stcs streaming).
// ---------------------------------------------------------------------------
__global__ __launch_bounds__(256, 8)
void se_scale_kernel(const float* __restrict__ x, const float* __restrict__ b2,
                     float* __restrict__ out) {
    cudaGridDependencySynchronize();         // excite's g_gp now visible

    const int rid = (NTOTAL - 1) - blockIdx.x;   // reversed traversal
    const int b   = rid / NSPLIT;
    const int blk = rid % NSPLIT;
    const int t = threadIdx.x;

    // gate for this thread's fixed 4-channel group (g_gp/b2 are L2-hot)
    const int c4 = (t * 4) & (C - 1);
    float4 g4;
    {
        float4 a = *reinterpret_cast<const float4*>(b2 + c4);
#pragma unroll
        for (int j = 0; j < RBLKS; j++) {
            float4 p = *reinterpret_cast<const float4*>(g_gp + ((size_t)b * RBLKS + j) * C + c4);
            a.x += p.x; a.y += p.y; a.z += p.z; a.w += p.w;
        }
        g4.x = 1.0f / (1.0f + __expf(-a.x));
        g4.y = 1.0f / (1.0f + __expf(-a.y));
        g4.z = 1.0f / (1.0f + __expf(-a.z));
        g4.w = 1.0f / (1.0f + __expf(-a.w));
    }

    const size_t base = (size_t)b * F4_PER_B + (size_t)blk * F4_PER_BLK;
    const float4* __restrict__ xi = reinterpret_cast<const float4*>(x) + base;
    float4* __restrict__ xo = reinterpret_cast<float4*>(out) + base;

#pragma unroll
    for (int i = 0; i < 16; i++) {
        float4 v = __ldcs(&xi[t + i * 256]);   // dead after use: evict-first
        v.x *= g4.x; v.y *= g4.y; v.z *= g4.z; v.w *= g4.w;
        __stcs(&xo[t + i * 256], v);           // streaming store
    }
}

extern "C" void kernel_launch(void* const* d_in, const int* in_sizes, int n_in,
                              void* d_out, int out_size) {
    const float* x  = (const float*)d_in[0];
    const float* w1 = (const float*)d_in[1];
    const float* b1 = (const float*)d_in[2];
    const float* w2 = (const float*)d_in[3];
    const float* b2 = (const float*)d_in[4];
    float* out = (float*)d_out;

    // Kernel 1: normal launch
    se_pool_kernel<<<dim3(NSPLIT, B), 256>>>(x);

    // Kernels 2 & 3: PDL dependents (overlap launch/prologue with producer tail)
    cudaLaunchAttribute attr[1];
    attr[0].id = cudaLaunchAttributeProgrammaticStreamSerialization;
    attr[0].val.programmaticStreamSerializationAllowed = 1;

    {
        cudaLaunchConfig_t cfg = {};
        cfg.gridDim  = dim3(RBLKS, B);
        cfg.blockDim = dim3(128, 1, 1);
        cfg.attrs = attr;
        cfg.numAttrs = 1;
        cudaLaunchKernelEx(&cfg, se_excite_kernel, w1, b1, w2);
    }
    {
        cudaLaunchConfig_t cfg = {};
        cfg.gridDim  = dim3(NTOTAL, 1, 1);
        cfg.blockDim = dim3(256, 1, 1);
        cfg.attrs = attr;
        cfg.numAttrs = 1;
        cudaLaunchKernelEx(&cfg, se_scale_kernel, x, b2, out);
    }
}